// round 15
// baseline (speedup 1.0000x reference)
#include <cuda_runtime.h>
#include <cuda_fp16.h>
#include <math.h>
#include <stdint.h>

#define B_   8
#define N1_  4096
#define N2_  256
#define D_   1024
#define INNER_ 1024
#define HEADS_ 16
#define DH_  64
#define L_   (N1_ + N2_)
#define EPS_ 1e-5f

__device__ __half g_kvin16[(size_t)B_ * L_ * D_];
__device__ __half g_latm16[(size_t)B_ * N2_ * D_];
__device__ __half g_wq16 [(size_t)INNER_ * D_];
__device__ __half g_wkv16[(size_t)2 * INNER_ * D_];
__device__ __half g_wo16 [(size_t)D_ * INNER_];
__device__ __half g_att16[(size_t)B_ * N2_ * INNER_];
__device__ __half g_q16[(size_t)B_ * N2_ * INNER_];
__device__ __half g_k16[(size_t)B_ * L_ * INNER_];
__device__ __half g_v16[(size_t)B_ * L_ * INNER_];

__device__ __forceinline__ uint32_t smem_u32(const void* p) {
    uint32_t a;
    asm("{ .reg .u64 t; cvta.to.shared.u64 t, %1; cvt.u32.u64 %0, t; }" : "=r"(a) : "l"(p));
    return a;
}
#define CP_ASYNC16(dst, src) \
    asm volatile("cp.async.cg.shared.global [%0], [%1], 16;" :: "r"(dst), "l"(src))
#define CP_COMMIT() asm volatile("cp.async.commit_group;" ::: "memory")
#define CP_WAIT(n)  asm volatile("cp.async.wait_group %0;" :: "n"(n) : "memory")
#define LDSM_X4(r, addr) \
    asm volatile("ldmatrix.sync.aligned.m8n8.x4.shared.b16 {%0,%1,%2,%3}, [%4];" \
                 : "=r"((r)[0]), "=r"((r)[1]), "=r"((r)[2]), "=r"((r)[3]) : "r"(addr))
#define LDSM_X4_T(r, addr) \
    asm volatile("ldmatrix.sync.aligned.m8n8.x4.trans.shared.b16 {%0,%1,%2,%3}, [%4];" \
                 : "=r"((r)[0]), "=r"((r)[1]), "=r"((r)[2]), "=r"((r)[3]) : "r"(addr))
#define MMAF16(acc, a, b0, b1) \
    asm volatile("mma.sync.aligned.m16n8k16.row.col.f32.f16.f16.f32 " \
        "{%0,%1,%2,%3}, {%4,%5,%6,%7}, {%8,%9}, {%0,%1,%2,%3};" \
        : "+f"((acc)[0]), "+f"((acc)[1]), "+f"((acc)[2]), "+f"((acc)[3]) \
        : "r"((a)[0]), "r"((a)[1]), "r"((a)[2]), "r"((a)[3]), "r"(b0), "r"(b1))

#define GS_ROWB  80
#define GSA      10240
#define GS_STAGE 30720

// =============== fused projection kernel: 512 threads, CTA 128x256, warp 32x64 ===============
__global__ __launch_bounds__(512, 1)
void proj_kernel(const __half* __restrict__ kvin16, const __half* __restrict__ latm16,
                 const __half* __restrict__ wkv16, const __half* __restrict__ wq16,
                 __half* __restrict__ k16, __half* __restrict__ v16,
                 __half* __restrict__ q16)
{
    extern __shared__ char smraw[];
    const uint32_t smbase = smem_u32(smraw);
    const int tid = threadIdx.x, wid = tid >> 5, lane = tid & 31;
    const int wm = (wid & 3) * 32, wn = (wid >> 2) * 64;
    const int K = D_;

    const bool is_q = blockIdx.x < 64;
    int bm, bn;
    const __half *A, *Bw;
    if (is_q) {
        bm = (blockIdx.x >> 2) * 128; bn = (blockIdx.x & 3) * 256;
        A = latm16; Bw = wq16;
    } else {
        const int j = blockIdx.x - 64;
        bm = (j >> 3) * 128; bn = (j & 7) * 256;
        A = kvin16; Bw = wkv16;
    }

    auto load_stage = [&](int kt, int st) {
        const uint32_t sb = smbase + st * GS_STAGE;
        #pragma unroll
        for (int it = 0; it < 3; it++) {
            const int c = tid + it * 512;       // 0..1535
            const bool isA = c < 512;
            const int cc = isA ? c : c - 512;
            const int row = cc >> 2, col = cc & 3;
            const char* src = (isA
                ? (const char*)A  + ((size_t)(bm + row) * K + kt * 32) * 2
                : (const char*)Bw + ((size_t)(bn + row) * K + kt * 32) * 2) + col * 16;
            CP_ASYNC16(sb + (isA ? 0u : (uint32_t)GSA) + row * GS_ROWB + col * 16, src);
        }
        CP_COMMIT();
    };

    float acc[2][8][4];
    #pragma unroll
    for (int i = 0; i < 2; i++)
        #pragma unroll
        for (int t = 0; t < 8; t++)
            #pragma unroll
            for (int c = 0; c < 4; c++) acc[i][t][c] = 0.f;

    const int niter = K / 32;
    load_stage(0, 0);
    load_stage(1, 1);

    for (int kt = 0; kt < niter; kt++) {
        const int st = kt % 3;
        CP_WAIT(1);
        __syncthreads();
        if (kt + 2 < niter) load_stage(kt + 2, (kt + 2) % 3);

        const uint32_t base = smbase + st * GS_STAGE;
        #pragma unroll
        for (int kk = 0; kk < 2; kk++) {
            uint32_t af[2][4], bf[4][4];
            #pragma unroll
            for (int i = 0; i < 2; i++) {
                const uint32_t ra = base + (uint32_t)((wm + i * 16 + (lane & 15)) * GS_ROWB
                                    + ((lane >> 4) << 4) + kk * 32);
                LDSM_X4(af[i], ra);
            }
            #pragma unroll
            for (int g = 0; g < 4; g++) {
                const uint32_t rb = base + GSA
                    + (uint32_t)((wn + g * 16 + ((lane >> 4) << 3) + (lane & 7)) * GS_ROWB
                                 + (((lane >> 3) & 1) << 4) + kk * 32);
                LDSM_X4(bf[g], rb);
            }
            #pragma unroll
            for (int i = 0; i < 2; i++)
                #pragma unroll
                for (int g = 0; g < 4; g++) {
                    MMAF16(acc[i][2*g],   af[i], bf[g][0], bf[g][1]);
                    MMAF16(acc[i][2*g+1], af[i], bf[g][2], bf[g][3]);
                }
        }
        __syncthreads();
    }

    #pragma unroll
    for (int i = 0; i < 2; i++)
        #pragma unroll
        for (int t = 0; t < 8; t++) {
            const int r0 = bm + wm + i * 16 + (lane >> 2);
            const int c  = bn + wn + t * 8 + (lane & 3) * 2;
            const float v0 = acc[i][t][0], v1 = acc[i][t][1];
            const float v2 = acc[i][t][2], v3 = acc[i][t][3];
            if (is_q) {
                *reinterpret_cast<__half2*>(&q16[(size_t)r0*INNER_ + c]) = __floats2half2_rn(v0, v1);
                *reinterpret_cast<__half2*>(&q16[(size_t)(r0+8)*INNER_ + c]) = __floats2half2_rn(v2, v3);
            } else {
                __half* dst = (c < INNER_) ? k16 : v16;
                const int cc = (c < INNER_) ? c : c - INNER_;
                *reinterpret_cast<__half2*>(&dst[(size_t)r0*INNER_ + cc]) = __floats2half2_rn(v0, v1);
                *reinterpret_cast<__half2*>(&dst[(size_t)(r0+8)*INNER_ + cc]) = __floats2half2_rn(v2, v3);
            }
        }
}

// =============== o-projection kernel: CTA 128x128, warp 32x64 (4x2), 128 CTAs ===============
#define OG_STAGE 20480

__global__ __launch_bounds__(256, 1)
void ogemm_kernel(const __half* __restrict__ att16, const __half* __restrict__ wo16,
                  float* __restrict__ out)
{
    extern __shared__ char smraw[];
    const uint32_t smbase = smem_u32(smraw);
    const int tid = threadIdx.x, wid = tid >> 5, lane = tid & 31;
    const int bm = blockIdx.y * 128, bn = blockIdx.x * 128;
    const int wm = (wid & 3) * 32, wn = (wid >> 2) * 64;
    const int K = INNER_;

    auto load_stage = [&](int kt, int st) {
        const uint32_t sb = smbase + st * OG_STAGE;
        #pragma unroll
        for (int it = 0; it < 4; it++) {
            const int c = tid + it * 256;
            const bool isA = c < 512;
            const int cc = isA ? c : c - 512;
            const int row = cc >> 2, col = cc & 3;
            const char* src = (isA
                ? (const char*)att16 + ((size_t)(bm + row) * K + kt * 32) * 2
                : (const char*)wo16  + ((size_t)(bn + row) * K + kt * 32) * 2) + col * 16;
            CP_ASYNC16(sb + (isA ? 0u : (uint32_t)GSA) + row * GS_ROWB + col * 16, src);
        }
        CP_COMMIT();
    };

    float acc[2][8][4];
    #pragma unroll
    for (int i = 0; i < 2; i++)
        #pragma unroll
        for (int t = 0; t < 8; t++)
            #pragma unroll
            for (int c = 0; c < 4; c++) acc[i][t][c] = 0.f;

    const int niter = K / 32;
    load_stage(0, 0);
    load_stage(1, 1);

    for (int kt = 0; kt < niter; kt++) {
        const int st = kt % 3;
        CP_WAIT(1);
        __syncthreads();
        if (kt + 2 < niter) load_stage(kt + 2, (kt + 2) % 3);

        const uint32_t base = smbase + st * OG_STAGE;
        #pragma unroll
        for (int kk = 0; kk < 2; kk++) {
            uint32_t af[2][4], bf[4][4];
            #pragma unroll
            for (int i = 0; i < 2; i++) {
                const uint32_t ra = base + (uint32_t)((wm + i * 16 + (lane & 15)) * GS_ROWB
                                    + ((lane >> 4) << 4) + kk * 32);
                LDSM_X4(af[i], ra);
            }
            #pragma unroll
            for (int g = 0; g < 4; g++) {
                const uint32_t rb = base + GSA
                    + (uint32_t)((wn + g * 16 + ((lane >> 4) << 3) + (lane & 7)) * GS_ROWB
                                 + (((lane >> 3) & 1) << 4) + kk * 32);
                LDSM_X4(bf[g], rb);
            }
            #pragma unroll
            for (int i = 0; i < 2; i++)
                #pragma unroll
                for (int g = 0; g < 4; g++) {
                    MMAF16(acc[i][2*g],   af[i], bf[g][0], bf[g][1]);
                    MMAF16(acc[i][2*g+1], af[i], bf[g][2], bf[g][3]);
                }
        }
        __syncthreads();
    }

    #pragma unroll
    for (int i = 0; i < 2; i++)
        #pragma unroll
        for (int t = 0; t < 8; t++) {
            const int r0 = bm + wm + i * 16 + (lane >> 2);
            const int c  = bn + wn + t * 8 + (lane & 3) * 2;
            *reinterpret_cast<float2*>(&out[(size_t)r0 * D_ + c]) =
                make_float2(acc[i][t][0], acc[i][t][1]);
            *reinterpret_cast<float2*>(&out[(size_t)(r0 + 8) * D_ + c]) =
                make_float2(acc[i][t][2], acc[i][t][3]);
        }
}

// =============== fused prep: LayerNorm(+mod) blocks + weight-conv blocks ===============
__global__ __launch_bounds__(256)
void prep_kernel(const float* __restrict__ x, const float* __restrict__ latents,
                 const float* __restrict__ shift, const float* __restrict__ scale,
                 const float* __restrict__ ln1w, const float* __restrict__ ln1b,
                 const float* __restrict__ ln2w, const float* __restrict__ ln2b,
                 const float* __restrict__ Wq, const float* __restrict__ Wkv,
                 const float* __restrict__ Wo, float qsc)
{
    const int t = threadIdx.x;
    if (blockIdx.x >= (unsigned)(B_ * L_)) {
        const int cb = blockIdx.x - B_ * L_;
        const float* s; __half* d; float sc; int i;
        if (cb < 1024)      { s = Wq;  d = g_wq16;  sc = qsc; i = cb * 256 + t; }
        else if (cb < 3072) { s = Wkv; d = g_wkv16; sc = 1.f; i = (cb - 1024) * 256 + t; }
        else                { s = Wo;  d = g_wo16;  sc = 1.f; i = (cb - 3072) * 256 + t; }
        float4 v = reinterpret_cast<const float4*>(s)[i];
        reinterpret_cast<__half2*>(d)[i*2]   = __floats2half2_rn(v.x * sc, v.y * sc);
        reinterpret_cast<__half2*>(d)[i*2+1] = __floats2half2_rn(v.z * sc, v.w * sc);
        return;
    }

    const int row = blockIdx.x, batch = row / L_, local = row % L_;
    const bool is_lat = (local >= N1_);
    const float* src = is_lat
        ? latents + ((size_t)batch * N2_ + (local - N1_)) * D_
        : x + ((size_t)batch * N1_ + local) * D_;

    float4 v = reinterpret_cast<const float4*>(src)[t];
    float s = v.x + v.y + v.z + v.w;
    float sq = v.x*v.x + v.y*v.y + v.z*v.z + v.w*v.w;

    __shared__ float red[16], red2[16];
    for (int o = 16; o > 0; o >>= 1) {
        s  += __shfl_down_sync(0xffffffff, s, o);
        sq += __shfl_down_sync(0xffffffff, sq, o);
    }
    int warp = t >> 5, lane = t & 31;
    if (lane == 0) { red[warp] = s; red2[warp] = sq; }
    __syncthreads();
    if (warp == 0) {
        s = (lane < 8) ? red[lane] : 0.f;
        sq = (lane < 8) ? red2[lane] : 0.f;
        for (int o = 4; o > 0; o >>= 1) {
            s  += __shfl_down_sync(0xffffffff, s, o);
            sq += __shfl_down_sync(0xffffffff, sq, o);
        }
        if (lane == 0) { red[0] = s; red2[0] = sq; }
    }
    __syncthreads();
    const float mu = red[0] * (1.0f / D_);
    const float var = red2[0] * (1.0f / D_) - mu * mu;
    const float rstd = rsqrtf(var + EPS_);

    float4 w4, b4, out;
    if (is_lat) {
        w4 = reinterpret_cast<const float4*>(ln2w)[t];
        b4 = reinterpret_cast<const float4*>(ln2b)[t];
    } else {
        w4 = reinterpret_cast<const float4*>(ln1w)[t];
        b4 = reinterpret_cast<const float4*>(ln1b)[t];
    }
    out.x = (v.x - mu) * rstd * w4.x + b4.x;
    out.y = (v.y - mu) * rstd * w4.y + b4.y;
    out.z = (v.z - mu) * rstd * w4.z + b4.z;
    out.w = (v.w - mu) * rstd * w4.w + b4.w;

    if (is_lat) {
        const float4 sc = reinterpret_cast<const float4*>(scale + (size_t)batch * D_)[t];
        const float4 sh = reinterpret_cast<const float4*>(shift + (size_t)batch * D_)[t];
        out.x = out.x * (1.0f + sc.x) + sh.x;
        out.y = out.y * (1.0f + sc.y) + sh.y;
        out.z = out.z * (1.0f + sc.z) + sh.z;
        out.w = out.w * (1.0f + sc.w) + sh.w;
    }

    __half2 hA = __floats2half2_rn(out.x, out.y);
    __half2 hB = __floats2half2_rn(out.z, out.w);
    {
        __half2* hp = reinterpret_cast<__half2*>(g_kvin16 + (size_t)row * D_);
        hp[t*2] = hA; hp[t*2+1] = hB;
    }
    if (is_lat) {
        const size_t lr = (size_t)batch * N2_ + (local - N1_);
        __half2* hp = reinterpret_cast<__half2*>(g_latm16 + lr * D_);
        hp[t*2] = hA; hp[t*2+1] = hB;
    }
}

// ============================ mma.sync flash attention (unchanged) ============================
#define AT_ROWB 144
#define AK_BASE 18432
#define AK_STAGE 18432
#define AV 9216
#define A_SMEM (18432 + 3 * 18432)

__global__ __launch_bounds__(256, 1)
void attn_mma(const __half* __restrict__ q16, const __half* __restrict__ k16,
              const __half* __restrict__ v16, __half* __restrict__ att)
{
    extern __shared__ char sm[];
    const uint32_t smb = smem_u32(sm);
    const int tid = threadIdx.x, wid = tid >> 5, lane = tid & 31;
    const int batch = blockIdx.x >> 4, head = blockIdx.x & 15;
    const int q0 = batch * N2_ + blockIdx.y * 128;
    const size_t kv0 = (size_t)batch * L_;

    for (int i = tid; i < 1024; i += 256) {
        const int row = i >> 3, ch = (i & 7) * 16;
        const size_t g = ((size_t)(q0 + row) * INNER_ + head * DH_) * 2;
        CP_ASYNC16(smb + row * AT_ROWB + ch, (const char*)q16 + g + ch);
    }
    CP_COMMIT();

    auto load_kv = [&](int t, int st) {
        const uint32_t sb = smb + AK_BASE + st * AK_STAGE;
        for (int i = tid; i < 512; i += 256) {
            const int row = i >> 3, ch = (i & 7) * 16;
            const size_t gr = kv0 + t * 64 + row;
            const size_t gk = (gr * INNER_ + head * DH_) * 2;
            CP_ASYNC16(sb + row * AT_ROWB + ch, (const char*)k16 + gk + ch);
            CP_ASYNC16(sb + AV + row * AT_ROWB + ch, (const char*)v16 + gk + ch);
        }
        CP_COMMIT();
    };

    const int NT = L_ / 64;
    load_kv(0, 0);
    load_kv(1, 1);
    CP_WAIT(1);
    __syncthreads();

    uint32_t qf[4][4];
    #pragma unroll
    for (int kk = 0; kk < 4; kk++) {
        const uint32_t ra = smb + (wid * 16 + (lane & 15)) * AT_ROWB + ((lane >> 4) << 4) + kk * 32;
        LDSM_X4(qf[kk], ra);
    }

    float accO[8][4];
    #pragma unroll
    for (int nt = 0; nt < 8; nt++)
        #pragma unroll
        for (int c = 0; c < 4; c++) accO[nt][c] = 0.f;
    float m0 = -1e30f, m1 = -1e30f, l0 = 0.f, l1 = 0.f;

    for (int t = 0; t < NT; t++) {
        if (t > 0) { CP_WAIT(1); __syncthreads(); }
        if (t + 2 < NT) load_kv(t + 2, (t + 2) % 3);
        const uint32_t sb = smb + AK_BASE + (t % 3) * AK_STAGE;

        float sacc[8][4];
        #pragma unroll
        for (int nt = 0; nt < 8; nt++)
            #pragma unroll
            for (int c = 0; c < 4; c++) sacc[nt][c] = 0.f;

        #pragma unroll
        for (int kk = 0; kk < 4; kk++) {
            uint32_t kb[4][4];
            #pragma unroll
            for (int g = 0; g < 4; g++) {
                const uint32_t rb = sb + (g * 16 + ((lane >> 4) << 3) + (lane & 7)) * AT_ROWB
                                    + (((lane >> 3) & 1) << 4) + kk * 32;
                LDSM_X4(kb[g], rb);
            }
            #pragma unroll
            for (int g = 0; g < 4; g++) {
                MMAF16(sacc[2*g],   qf[kk], kb[g][0], kb[g][1]);
                MMAF16(sacc[2*g+1], qf[kk], kb[g][2], kb[g][3]);
            }
        }

        float tm0 = sacc[0][0], tm1 = sacc[0][2];
        #pragma unroll
        for (int nt = 0; nt < 8; nt++) {
            tm0 = fmaxf(tm0, fmaxf(sacc[nt][0], sacc[nt][1]));
            tm1 = fmaxf(tm1, fmaxf(sacc[nt][2], sacc[nt][3]));
        }
        tm0 = fmaxf(tm0, __shfl_xor_sync(0xffffffff, tm0, 1));
        tm0 = fmaxf(tm0, __shfl_xor_sync(0xffffffff, tm0, 2));
        tm1 = fmaxf(tm1, __shfl_xor_sync(0xffffffff, tm1, 1));
        tm1 = fmaxf(tm1, __shfl_xor_sync(0xffffffff, tm1, 2));

        const float mn0 = fmaxf(m0, tm0), mn1 = fmaxf(m1, tm1);
        const float c0 = exp2f(m0 - mn0), c1 = exp2f(m1 - mn1);
        m0 = mn0; m1 = mn1;

        float ls0 = 0.f, ls1 = 0.f;
        uint32_t pa[4][4];
        #pragma unroll
        for (int nt = 0; nt < 8; nt++) {
            const float p0 = exp2f(sacc[nt][0] - mn0);
            const float p1 = exp2f(sacc[nt][1] - mn0);
            const float p2 = exp2f(sacc[nt][2] - mn1);
            const float p3 = exp2f(sacc[nt][3] - mn1);
            ls0 += p0 + p1; ls1 += p2 + p3;
            __half2 ha = __floats2half2_rn(p0, p1);
            __half2 hb = __floats2half2_rn(p2, p3);
            pa[nt >> 1][(nt & 1) * 2 + 0] = *reinterpret_cast<uint32_t*>(&ha);
            pa[nt >> 1][(nt & 1) * 2 + 1] = *reinterpret_cast<uint32_t*>(&hb);
        }
        l0 = l0 * c0 + ls0;
        l1 = l1 * c1 + ls1;
        #pragma unroll
        for (int nt = 0; nt < 8; nt++) {
            accO[nt][0] *= c0; accO[nt][1] *= c0;
            accO[nt][2] *= c1; accO[nt][3] *= c1;
        }

        #pragma unroll
        for (int kt = 0; kt < 4; kt++) {
            uint32_t vb[4][4];
            #pragma unroll
            for (int g = 0; g < 4; g++) {
                const uint32_t rv = sb + AV + (kt * 16 + (lane & 15)) * AT_ROWB
                                    + g * 32 + ((lane >> 4) << 4);
                LDSM_X4_T(vb[g], rv);
            }
            #pragma unroll
            for (int g = 0; g < 4; g++) {
                MMAF16(accO[2*g],   pa[kt], vb[g][0], vb[g][1]);
                MMAF16(accO[2*g+1], pa[kt], vb[g][2], vb[g][3]);
            }
        }
    }

    l0 += __shfl_xor_sync(0xffffffff, l0, 1);
    l0 += __shfl_xor_sync(0xffffffff, l0, 2);
    l1 += __shfl_xor_sync(0xffffffff, l1, 1);
    l1 += __shfl_xor_sync(0xffffffff, l1, 2);
    const float i0 = 1.0f / l0, i1 = 1.0f / l1;

    const int qrow = q0 + wid * 16 + (lane >> 2);
    #pragma unroll
    for (int nt = 0; nt < 8; nt++) {
        const int col = head * DH_ + nt * 8 + (lane & 3) * 2;
        *reinterpret_cast<__half2*>(att + (size_t)qrow*INNER_ + col) =
            __floats2half2_rn(accO[nt][0]*i0, accO[nt][1]*i0);
        *reinterpret_cast<__half2*>(att + (size_t)(qrow+8)*INNER_ + col) =
            __floats2half2_rn(accO[nt][2]*i1, accO[nt][3]*i1);
    }
}

// ---------------- launch ----------------
extern "C" void kernel_launch(void* const* d_in, const int* in_sizes, int n_in,
                              void* d_out, int out_size)
{
    const float* x       = (const float*)d_in[0];
    const float* latents = (const float*)d_in[1];
    const float* shift   = (const float*)d_in[2];
    const float* scale   = (const float*)d_in[3];
    const float* ln1w    = (const float*)d_in[4];
    const float* ln1b    = (const float*)d_in[5];
    const float* ln2w    = (const float*)d_in[6];
    const float* ln2b    = (const float*)d_in[7];
    const float* Wq      = (const float*)d_in[8];
    const float* Wkv     = (const float*)d_in[9];
    const float* Wo      = (const float*)d_in[10];
    float* out = (float*)d_out;

    __half *kvin16,*latm16,*wq16,*wkv16,*wo16,*att16,*q16,*k16,*v16;
    cudaGetSymbolAddress((void**)&kvin16, g_kvin16);
    cudaGetSymbolAddress((void**)&latm16, g_latm16);
    cudaGetSymbolAddress((void**)&wq16, g_wq16);
    cudaGetSymbolAddress((void**)&wkv16, g_wkv16);
    cudaGetSymbolAddress((void**)&wo16, g_wo16);
    cudaGetSymbolAddress((void**)&att16, g_att16);
    cudaGetSymbolAddress((void**)&q16, g_q16);
    cudaGetSymbolAddress((void**)&k16, g_k16);
    cudaGetSymbolAddress((void**)&v16, g_v16);

    cudaFuncSetAttribute(proj_kernel, cudaFuncAttributeMaxDynamicSharedMemorySize, 3 * GS_STAGE);
    cudaFuncSetAttribute(ogemm_kernel, cudaFuncAttributeMaxDynamicSharedMemorySize, 3 * OG_STAGE);
    cudaFuncSetAttribute(attn_mma, cudaFuncAttributeMaxDynamicSharedMemorySize, A_SMEM);

    const float qsc = 0.125f * 1.44269504088896340736f;  // attn_scale^2 * log2(e)

    // 1) fused LN + weight conversions
    prep_kernel<<<B_ * L_ + 4096, 256>>>(x, latents, shift, scale,
                                         ln1w, ln1b, ln2w, ln2b, Wq, Wkv, Wo, qsc);

    // 2) fused q + kv projections (512 threads)
    proj_kernel<<<64 + 2176, 512, 3 * GS_STAGE>>>(kvin16, latm16, wkv16, wq16,
                                                  k16, v16, q16);

    // 3) attention
    {
        dim3 grid(B_ * HEADS_, N2_ / 128);
        attn_mma<<<grid, 256, A_SMEM>>>(q16, k16, v16, att16);
    }

    // 4) out = att @ Wo^T (fp32)
    {
        dim3 grid(D_ / 128, (B_ * N2_) / 128);
        ogemm_kernel<<<grid, 256, 3 * OG_STAGE>>>(att16, wo16, out);
    }
    (void)in_sizes; (void)n_in; (void)out_size;
}

// round 16
// speedup vs baseline: 1.0070x; 1.0070x over previous
#include <cuda_runtime.h>
#include <cuda_fp16.h>
#include <math.h>
#include <stdint.h>

#define B_   8
#define N1_  4096
#define N2_  256
#define D_   1024
#define INNER_ 1024
#define HEADS_ 16
#define DH_  64
#define L_   (N1_ + N2_)
#define EPS_ 1e-5f

__device__ __half g_kvin16[(size_t)B_ * L_ * D_];
__device__ __half g_latm16[(size_t)B_ * N2_ * D_];
__device__ __half g_wq16 [(size_t)INNER_ * D_];
__device__ __half g_wkv16[(size_t)2 * INNER_ * D_];
__device__ __half g_wo16 [(size_t)D_ * INNER_];
__device__ __half g_att16[(size_t)B_ * N2_ * INNER_];
__device__ __half g_q16[(size_t)B_ * N2_ * INNER_];
__device__ __half g_k16[(size_t)B_ * L_ * INNER_];
__device__ __half g_v16[(size_t)B_ * L_ * INNER_];

__device__ __forceinline__ uint32_t smem_u32(const void* p) {
    uint32_t a;
    asm("{ .reg .u64 t; cvta.to.shared.u64 t, %1; cvt.u32.u64 %0, t; }" : "=r"(a) : "l"(p));
    return a;
}
#define CP_ASYNC16(dst, src) \
    asm volatile("cp.async.cg.shared.global [%0], [%1], 16;" :: "r"(dst), "l"(src))
#define CP_COMMIT() asm volatile("cp.async.commit_group;" ::: "memory")
#define CP_WAIT(n)  asm volatile("cp.async.wait_group %0;" :: "n"(n) : "memory")
#define LDSM_X4(r, addr) \
    asm volatile("ldmatrix.sync.aligned.m8n8.x4.shared.b16 {%0,%1,%2,%3}, [%4];" \
                 : "=r"((r)[0]), "=r"((r)[1]), "=r"((r)[2]), "=r"((r)[3]) : "r"(addr))
#define LDSM_X4_T(r, addr) \
    asm volatile("ldmatrix.sync.aligned.m8n8.x4.trans.shared.b16 {%0,%1,%2,%3}, [%4];" \
                 : "=r"((r)[0]), "=r"((r)[1]), "=r"((r)[2]), "=r"((r)[3]) : "r"(addr))
#define MMAF16(acc, a, b0, b1) \
    asm volatile("mma.sync.aligned.m16n8k16.row.col.f32.f16.f16.f32 " \
        "{%0,%1,%2,%3}, {%4,%5,%6,%7}, {%8,%9}, {%0,%1,%2,%3};" \
        : "+f"((acc)[0]), "+f"((acc)[1]), "+f"((acc)[2]), "+f"((acc)[3]) \
        : "r"((a)[0]), "r"((a)[1]), "r"((a)[2]), "r"((a)[3]), "r"(b0), "r"(b1))

#define GS_ROWB  80
#define GSA      10240
#define GS_STAGE 30720

// =============== GEMM core 128x256 (R14-proven: 256 threads, warp 64x64) ===============
struct GemmAcc { float a[4][8][4]; };

__device__ __forceinline__ void gemm_tile(
    const __half* __restrict__ A16, const __half* __restrict__ B16,
    int bm, int bn, uint32_t smbase, GemmAcc& G)
{
    const int tid = threadIdx.x, wid = tid >> 5, lane = tid & 31;
    const int wm = (wid & 1) * 64, wn = (wid >> 1) * 64;
    const int K = D_;

    auto load_stage = [&](int kt, int st) {
        const uint32_t sb = smbase + st * GS_STAGE;
        #pragma unroll
        for (int it = 0; it < 6; it++) {
            const int c = tid + it * 256;
            const bool isA = c < 512;
            const int cc = isA ? c : c - 512;
            const int row = cc >> 2, col = cc & 3;
            const char* src = (isA
                ? (const char*)A16 + ((size_t)(bm + row) * K + kt * 32) * 2
                : (const char*)B16 + ((size_t)(bn + row) * K + kt * 32) * 2) + col * 16;
            CP_ASYNC16(sb + (isA ? 0u : (uint32_t)GSA) + row * GS_ROWB + col * 16, src);
        }
        CP_COMMIT();
    };

    #pragma unroll
    for (int i = 0; i < 4; i++)
        #pragma unroll
        for (int t = 0; t < 8; t++)
            #pragma unroll
            for (int c = 0; c < 4; c++) G.a[i][t][c] = 0.f;

    const int niter = K / 32;
    load_stage(0, 0);
    load_stage(1, 1);

    for (int kt = 0; kt < niter; kt++) {
        const int st = kt % 3;
        CP_WAIT(1);
        __syncthreads();
        if (kt + 2 < niter) load_stage(kt + 2, (kt + 2) % 3);

        const uint32_t base = smbase + st * GS_STAGE;
        #pragma unroll
        for (int kk = 0; kk < 2; kk++) {
            uint32_t af[4][4], bf[4][4];
            #pragma unroll
            for (int i = 0; i < 4; i++) {
                const uint32_t ra = base + (uint32_t)((wm + i * 16 + (lane & 15)) * GS_ROWB
                                    + ((lane >> 4) << 4) + kk * 32);
                LDSM_X4(af[i], ra);
            }
            #pragma unroll
            for (int g = 0; g < 4; g++) {
                const uint32_t rb = base + GSA
                    + (uint32_t)((wn + g * 16 + ((lane >> 4) << 3) + (lane & 7)) * GS_ROWB
                                 + (((lane >> 3) & 1) << 4) + kk * 32);
                LDSM_X4(bf[g], rb);
            }
            #pragma unroll
            for (int i = 0; i < 4; i++)
                #pragma unroll
                for (int g = 0; g < 4; g++) {
                    MMAF16(G.a[i][2*g],   af[i], bf[g][0], bf[g][1]);
                    MMAF16(G.a[i][2*g+1], af[i], bf[g][2], bf[g][3]);
                }
        }
        __syncthreads();
    }
}

// =============== fused projection kernel: q (64 CTAs) + kv (2176 CTAs) ===============
__global__ __launch_bounds__(256, 1)
void proj_kernel(const __half* __restrict__ kvin16, const __half* __restrict__ latm16,
                 const __half* __restrict__ wkv16, const __half* __restrict__ wq16,
                 __half* __restrict__ k16, __half* __restrict__ v16,
                 __half* __restrict__ q16)
{
    extern __shared__ char smraw[];
    const uint32_t smbase = smem_u32(smraw);
    const int tid = threadIdx.x, wid = tid >> 5, lane = tid & 31;
    const int wm = (wid & 1) * 64, wn = (wid >> 1) * 64;

    const bool is_q = blockIdx.x < 64;
    int bm, bn;
    const __half *A, *Bw;
    if (is_q) {
        bm = (blockIdx.x >> 2) * 128; bn = (blockIdx.x & 3) * 256;
        A = latm16; Bw = wq16;
    } else {
        const int j = blockIdx.x - 64;
        bm = (j >> 3) * 128; bn = (j & 7) * 256;
        A = kvin16; Bw = wkv16;
    }

    GemmAcc G;
    gemm_tile(A, Bw, bm, bn, smbase, G);

    #pragma unroll
    for (int i = 0; i < 4; i++)
        #pragma unroll
        for (int t = 0; t < 8; t++) {
            const int r0 = bm + wm + i * 16 + (lane >> 2);
            const int c  = bn + wn + t * 8 + (lane & 3) * 2;
            const float v0 = G.a[i][t][0], v1 = G.a[i][t][1];
            const float v2 = G.a[i][t][2], v3 = G.a[i][t][3];
            if (is_q) {
                *reinterpret_cast<__half2*>(&q16[(size_t)r0*INNER_ + c]) = __floats2half2_rn(v0, v1);
                *reinterpret_cast<__half2*>(&q16[(size_t)(r0+8)*INNER_ + c]) = __floats2half2_rn(v2, v3);
            } else {
                __half* dst = (c < INNER_) ? k16 : v16;
                const int cc = (c < INNER_) ? c : c - INNER_;
                *reinterpret_cast<__half2*>(&dst[(size_t)r0*INNER_ + cc]) = __floats2half2_rn(v0, v1);
                *reinterpret_cast<__half2*>(&dst[(size_t)(r0+8)*INNER_ + cc]) = __floats2half2_rn(v2, v3);
            }
        }
}

// =============== o-projection kernel: CTA 128x128, warp 32x64 (4x2), 128 CTAs ===============
#define OG_STAGE 20480

__global__ __launch_bounds__(256, 1)
void ogemm_kernel(const __half* __restrict__ att16, const __half* __restrict__ wo16,
                  float* __restrict__ out)
{
    extern __shared__ char smraw[];
    const uint32_t smbase = smem_u32(smraw);
    const int tid = threadIdx.x, wid = tid >> 5, lane = tid & 31;
    const int bm = blockIdx.y * 128, bn = blockIdx.x * 128;
    const int wm = (wid & 3) * 32, wn = (wid >> 2) * 64;
    const int K = INNER_;

    auto load_stage = [&](int kt, int st) {
        const uint32_t sb = smbase + st * OG_STAGE;
        #pragma unroll
        for (int it = 0; it < 4; it++) {
            const int c = tid + it * 256;
            const bool isA = c < 512;
            const int cc = isA ? c : c - 512;
            const int row = cc >> 2, col = cc & 3;
            const char* src = (isA
                ? (const char*)att16 + ((size_t)(bm + row) * K + kt * 32) * 2
                : (const char*)wo16  + ((size_t)(bn + row) * K + kt * 32) * 2) + col * 16;
            CP_ASYNC16(sb + (isA ? 0u : (uint32_t)GSA) + row * GS_ROWB + col * 16, src);
        }
        CP_COMMIT();
    };

    float acc[2][8][4];
    #pragma unroll
    for (int i = 0; i < 2; i++)
        #pragma unroll
        for (int t = 0; t < 8; t++)
            #pragma unroll
            for (int c = 0; c < 4; c++) acc[i][t][c] = 0.f;

    const int niter = K / 32;
    load_stage(0, 0);
    load_stage(1, 1);

    for (int kt = 0; kt < niter; kt++) {
        const int st = kt % 3;
        CP_WAIT(1);
        __syncthreads();
        if (kt + 2 < niter) load_stage(kt + 2, (kt + 2) % 3);

        const uint32_t base = smbase + st * OG_STAGE;
        #pragma unroll
        for (int kk = 0; kk < 2; kk++) {
            uint32_t af[2][4], bf[4][4];
            #pragma unroll
            for (int i = 0; i < 2; i++) {
                const uint32_t ra = base + (uint32_t)((wm + i * 16 + (lane & 15)) * GS_ROWB
                                    + ((lane >> 4) << 4) + kk * 32);
                LDSM_X4(af[i], ra);
            }
            #pragma unroll
            for (int g = 0; g < 4; g++) {
                const uint32_t rb = base + GSA
                    + (uint32_t)((wn + g * 16 + ((lane >> 4) << 3) + (lane & 7)) * GS_ROWB
                                 + (((lane >> 3) & 1) << 4) + kk * 32);
                LDSM_X4(bf[g], rb);
            }
            #pragma unroll
            for (int i = 0; i < 2; i++)
                #pragma unroll
                for (int g = 0; g < 4; g++) {
                    MMAF16(acc[i][2*g],   af[i], bf[g][0], bf[g][1]);
                    MMAF16(acc[i][2*g+1], af[i], bf[g][2], bf[g][3]);
                }
        }
        __syncthreads();
    }

    #pragma unroll
    for (int i = 0; i < 2; i++)
        #pragma unroll
        for (int t = 0; t < 8; t++) {
            const int r0 = bm + wm + i * 16 + (lane >> 2);
            const int c  = bn + wn + t * 8 + (lane & 3) * 2;
            *reinterpret_cast<float2*>(&out[(size_t)r0 * D_ + c]) =
                make_float2(acc[i][t][0], acc[i][t][1]);
            *reinterpret_cast<float2*>(&out[(size_t)(r0 + 8) * D_ + c]) =
                make_float2(acc[i][t][2], acc[i][t][3]);
        }
}

// =============== fused prep: LayerNorm(+mod) blocks + weight-conv blocks ===============
__global__ __launch_bounds__(256)
void prep_kernel(const float* __restrict__ x, const float* __restrict__ latents,
                 const float* __restrict__ shift, const float* __restrict__ scale,
                 const float* __restrict__ ln1w, const float* __restrict__ ln1b,
                 const float* __restrict__ ln2w, const float* __restrict__ ln2b,
                 const float* __restrict__ Wq, const float* __restrict__ Wkv,
                 const float* __restrict__ Wo, float qsc)
{
    const int t = threadIdx.x;
    if (blockIdx.x >= (unsigned)(B_ * L_)) {
        const int cb = blockIdx.x - B_ * L_;
        const float* s; __half* d; float sc; int i;
        if (cb < 1024)      { s = Wq;  d = g_wq16;  sc = qsc; i = cb * 256 + t; }
        else if (cb < 3072) { s = Wkv; d = g_wkv16; sc = 1.f; i = (cb - 1024) * 256 + t; }
        else                { s = Wo;  d = g_wo16;  sc = 1.f; i = (cb - 3072) * 256 + t; }
        float4 v = reinterpret_cast<const float4*>(s)[i];
        reinterpret_cast<__half2*>(d)[i*2]   = __floats2half2_rn(v.x * sc, v.y * sc);
        reinterpret_cast<__half2*>(d)[i*2+1] = __floats2half2_rn(v.z * sc, v.w * sc);
        return;
    }

    const int row = blockIdx.x, batch = row / L_, local = row % L_;
    const bool is_lat = (local >= N1_);
    const float* src = is_lat
        ? latents + ((size_t)batch * N2_ + (local - N1_)) * D_
        : x + ((size_t)batch * N1_ + local) * D_;

    float4 v = reinterpret_cast<const float4*>(src)[t];
    float s = v.x + v.y + v.z + v.w;
    float sq = v.x*v.x + v.y*v.y + v.z*v.z + v.w*v.w;

    __shared__ float red[16], red2[16];
    for (int o = 16; o > 0; o >>= 1) {
        s  += __shfl_down_sync(0xffffffff, s, o);
        sq += __shfl_down_sync(0xffffffff, sq, o);
    }
    int warp = t >> 5, lane = t & 31;
    if (lane == 0) { red[warp] = s; red2[warp] = sq; }
    __syncthreads();
    if (warp == 0) {
        s = (lane < 8) ? red[lane] : 0.f;
        sq = (lane < 8) ? red2[lane] : 0.f;
        for (int o = 4; o > 0; o >>= 1) {
            s  += __shfl_down_sync(0xffffffff, s, o);
            sq += __shfl_down_sync(0xffffffff, sq, o);
        }
        if (lane == 0) { red[0] = s; red2[0] = sq; }
    }
    __syncthreads();
    const float mu = red[0] * (1.0f / D_);
    const float var = red2[0] * (1.0f / D_) - mu * mu;
    const float rstd = rsqrtf(var + EPS_);

    float4 w4, b4, out;
    if (is_lat) {
        w4 = reinterpret_cast<const float4*>(ln2w)[t];
        b4 = reinterpret_cast<const float4*>(ln2b)[t];
    } else {
        w4 = reinterpret_cast<const float4*>(ln1w)[t];
        b4 = reinterpret_cast<const float4*>(ln1b)[t];
    }
    out.x = (v.x - mu) * rstd * w4.x + b4.x;
    out.y = (v.y - mu) * rstd * w4.y + b4.y;
    out.z = (v.z - mu) * rstd * w4.z + b4.z;
    out.w = (v.w - mu) * rstd * w4.w + b4.w;

    if (is_lat) {
        const float4 sc = reinterpret_cast<const float4*>(scale + (size_t)batch * D_)[t];
        const float4 sh = reinterpret_cast<const float4*>(shift + (size_t)batch * D_)[t];
        out.x = out.x * (1.0f + sc.x) + sh.x;
        out.y = out.y * (1.0f + sc.y) + sh.y;
        out.z = out.z * (1.0f + sc.z) + sh.z;
        out.w = out.w * (1.0f + sc.w) + sh.w;
    }

    __half2 hA = __floats2half2_rn(out.x, out.y);
    __half2 hB = __floats2half2_rn(out.z, out.w);
    {
        __half2* hp = reinterpret_cast<__half2*>(g_kvin16 + (size_t)row * D_);
        hp[t*2] = hA; hp[t*2+1] = hB;
    }
    if (is_lat) {
        const size_t lr = (size_t)batch * N2_ + (local - N1_);
        __half2* hp = reinterpret_cast<__half2*>(g_latm16 + lr * D_);
        hp[t*2] = hA; hp[t*2+1] = hB;
    }
}

// ============================ mma.sync flash attention (fp16x2 exp) ============================
#define AT_ROWB 144
#define AK_BASE 18432
#define AK_STAGE 18432
#define AV 9216
#define A_SMEM (18432 + 3 * 18432)

__global__ __launch_bounds__(256, 1)
void attn_mma(const __half* __restrict__ q16, const __half* __restrict__ k16,
              const __half* __restrict__ v16, __half* __restrict__ att)
{
    extern __shared__ char sm[];
    const uint32_t smb = smem_u32(sm);
    const int tid = threadIdx.x, wid = tid >> 5, lane = tid & 31;
    const int batch = blockIdx.x >> 4, head = blockIdx.x & 15;
    const int q0 = batch * N2_ + blockIdx.y * 128;
    const size_t kv0 = (size_t)batch * L_;

    for (int i = tid; i < 1024; i += 256) {
        const int row = i >> 3, ch = (i & 7) * 16;
        const size_t g = ((size_t)(q0 + row) * INNER_ + head * DH_) * 2;
        CP_ASYNC16(smb + row * AT_ROWB + ch, (const char*)q16 + g + ch);
    }
    CP_COMMIT();

    auto load_kv = [&](int t, int st) {
        const uint32_t sb = smb + AK_BASE + st * AK_STAGE;
        for (int i = tid; i < 512; i += 256) {
            const int row = i >> 3, ch = (i & 7) * 16;
            const size_t gr = kv0 + t * 64 + row;
            const size_t gk = (gr * INNER_ + head * DH_) * 2;
            CP_ASYNC16(sb + row * AT_ROWB + ch, (const char*)k16 + gk + ch);
            CP_ASYNC16(sb + AV + row * AT_ROWB + ch, (const char*)v16 + gk + ch);
        }
        CP_COMMIT();
    };

    const int NT = L_ / 64;
    load_kv(0, 0);
    load_kv(1, 1);
    CP_WAIT(1);
    __syncthreads();

    uint32_t qf[4][4];
    #pragma unroll
    for (int kk = 0; kk < 4; kk++) {
        const uint32_t ra = smb + (wid * 16 + (lane & 15)) * AT_ROWB + ((lane >> 4) << 4) + kk * 32;
        LDSM_X4(qf[kk], ra);
    }

    float accO[8][4];
    #pragma unroll
    for (int nt = 0; nt < 8; nt++)
        #pragma unroll
        for (int c = 0; c < 4; c++) accO[nt][c] = 0.f;
    float m0 = -1e30f, m1 = -1e30f, l0 = 0.f, l1 = 0.f;

    for (int t = 0; t < NT; t++) {
        if (t > 0) { CP_WAIT(1); __syncthreads(); }
        if (t + 2 < NT) load_kv(t + 2, (t + 2) % 3);
        const uint32_t sb = smb + AK_BASE + (t % 3) * AK_STAGE;

        float sacc[8][4];
        #pragma unroll
        for (int nt = 0; nt < 8; nt++)
            #pragma unroll
            for (int c = 0; c < 4; c++) sacc[nt][c] = 0.f;

        #pragma unroll
        for (int kk = 0; kk < 4; kk++) {
            uint32_t kb[4][4];
            #pragma unroll
            for (int g = 0; g < 4; g++) {
                const uint32_t rb = sb + (g * 16 + ((lane >> 4) << 3) + (lane & 7)) * AT_ROWB
                                    + (((lane >> 3) & 1) << 4) + kk * 32;
                LDSM_X4(kb[g], rb);
            }
            #pragma unroll
            for (int g = 0; g < 4; g++) {
                MMAF16(sacc[2*g],   qf[kk], kb[g][0], kb[g][1]);
                MMAF16(sacc[2*g+1], qf[kk], kb[g][2], kb[g][3]);
            }
        }

        float tm0 = sacc[0][0], tm1 = sacc[0][2];
        #pragma unroll
        for (int nt = 0; nt < 8; nt++) {
            tm0 = fmaxf(tm0, fmaxf(sacc[nt][0], sacc[nt][1]));
            tm1 = fmaxf(tm1, fmaxf(sacc[nt][2], sacc[nt][3]));
        }
        tm0 = fmaxf(tm0, __shfl_xor_sync(0xffffffff, tm0, 1));
        tm0 = fmaxf(tm0, __shfl_xor_sync(0xffffffff, tm0, 2));
        tm1 = fmaxf(tm1, __shfl_xor_sync(0xffffffff, tm1, 1));
        tm1 = fmaxf(tm1, __shfl_xor_sync(0xffffffff, tm1, 2));

        const float mn0 = fmaxf(m0, tm0), mn1 = fmaxf(m1, tm1);
        const float c0 = exp2f(m0 - mn0), c1 = exp2f(m1 - mn1);
        m0 = mn0; m1 = mn1;

        float ls0 = 0.f, ls1 = 0.f;
        uint32_t pa[4][4];
        #pragma unroll
        for (int nt = 0; nt < 8; nt++) {
            // fp16x2 exponentials: halves MUFU ops and feeds PV directly
            __half2 e0 = h2exp2(__floats2half2_rn(sacc[nt][0] - mn0, sacc[nt][1] - mn0));
            __half2 e1 = h2exp2(__floats2half2_rn(sacc[nt][2] - mn1, sacc[nt][3] - mn1));
            float2 f0 = __half22float2(e0);
            float2 f1 = __half22float2(e1);
            ls0 += f0.x + f0.y;
            ls1 += f1.x + f1.y;
            pa[nt >> 1][(nt & 1) * 2 + 0] = *reinterpret_cast<uint32_t*>(&e0);
            pa[nt >> 1][(nt & 1) * 2 + 1] = *reinterpret_cast<uint32_t*>(&e1);
        }
        l0 = l0 * c0 + ls0;
        l1 = l1 * c1 + ls1;
        #pragma unroll
        for (int nt = 0; nt < 8; nt++) {
            accO[nt][0] *= c0; accO[nt][1] *= c0;
            accO[nt][2] *= c1; accO[nt][3] *= c1;
        }

        #pragma unroll
        for (int kt = 0; kt < 4; kt++) {
            uint32_t vb[4][4];
            #pragma unroll
            for (int g = 0; g < 4; g++) {
                const uint32_t rv = sb + AV + (kt * 16 + (lane & 15)) * AT_ROWB
                                    + g * 32 + ((lane >> 4) << 4);
                LDSM_X4_T(vb[g], rv);
            }
            #pragma unroll
            for (int g = 0; g < 4; g++) {
                MMAF16(accO[2*g],   pa[kt], vb[g][0], vb[g][1]);
                MMAF16(accO[2*g+1], pa[kt], vb[g][2], vb[g][3]);
            }
        }
    }

    l0 += __shfl_xor_sync(0xffffffff, l0, 1);
    l0 += __shfl_xor_sync(0xffffffff, l0, 2);
    l1 += __shfl_xor_sync(0xffffffff, l1, 1);
    l1 += __shfl_xor_sync(0xffffffff, l1, 2);
    const float i0 = 1.0f / l0, i1 = 1.0f / l1;

    const int qrow = q0 + wid * 16 + (lane >> 2);
    #pragma unroll
    for (int nt = 0; nt < 8; nt++) {
        const int col = head * DH_ + nt * 8 + (lane & 3) * 2;
        *reinterpret_cast<__half2*>(att + (size_t)qrow*INNER_ + col) =
            __floats2half2_rn(accO[nt][0]*i0, accO[nt][1]*i0);
        *reinterpret_cast<__half2*>(att + (size_t)(qrow+8)*INNER_ + col) =
            __floats2half2_rn(accO[nt][2]*i1, accO[nt][3]*i1);
    }
}

// ---------------- launch ----------------
extern "C" void kernel_launch(void* const* d_in, const int* in_sizes, int n_in,
                              void* d_out, int out_size)
{
    const float* x       = (const float*)d_in[0];
    const float* latents = (const float*)d_in[1];
    const float* shift   = (const float*)d_in[2];
    const float* scale   = (const float*)d_in[3];
    const float* ln1w    = (const float*)d_in[4];
    const float* ln1b    = (const float*)d_in[5];
    const float* ln2w    = (const float*)d_in[6];
    const float* ln2b    = (const float*)d_in[7];
    const float* Wq      = (const float*)d_in[8];
    const float* Wkv     = (const float*)d_in[9];
    const float* Wo      = (const float*)d_in[10];
    float* out = (float*)d_out;

    __half *kvin16,*latm16,*wq16,*wkv16,*wo16,*att16,*q16,*k16,*v16;
    cudaGetSymbolAddress((void**)&kvin16, g_kvin16);
    cudaGetSymbolAddress((void**)&latm16, g_latm16);
    cudaGetSymbolAddress((void**)&wq16, g_wq16);
    cudaGetSymbolAddress((void**)&wkv16, g_wkv16);
    cudaGetSymbolAddress((void**)&wo16, g_wo16);
    cudaGetSymbolAddress((void**)&att16, g_att16);
    cudaGetSymbolAddress((void**)&q16, g_q16);
    cudaGetSymbolAddress((void**)&k16, g_k16);
    cudaGetSymbolAddress((void**)&v16, g_v16);

    cudaFuncSetAttribute(proj_kernel, cudaFuncAttributeMaxDynamicSharedMemorySize, 3 * GS_STAGE);
    cudaFuncSetAttribute(ogemm_kernel, cudaFuncAttributeMaxDynamicSharedMemorySize, 3 * OG_STAGE);
    cudaFuncSetAttribute(attn_mma, cudaFuncAttributeMaxDynamicSharedMemorySize, A_SMEM);

    const float qsc = 0.125f * 1.44269504088896340736f;  // attn_scale^2 * log2(e)

    // 1) fused LN + weight conversions
    prep_kernel<<<B_ * L_ + 4096, 256>>>(x, latents, shift, scale,
                                         ln1w, ln1b, ln2w, ln2b, Wq, Wkv, Wo, qsc);

    // 2) fused q + kv projections (R14 config)
    proj_kernel<<<64 + 2176, 256, 3 * GS_STAGE>>>(kvin16, latm16, wkv16, wq16,
                                                  k16, v16, q16);

    // 3) attention
    {
        dim3 grid(B_ * HEADS_, N2_ / 128);
        attn_mma<<<grid, 256, A_SMEM>>>(q16, k16, v16, att16);
    }

    // 4) out = att @ Wo^T (fp32)
    {
        dim3 grid(D_ / 128, (B_ * N2_) / 128);
        ogemm_kernel<<<grid, 256, 3 * OG_STAGE>>>(att16, wo16, out);
    }
    (void)in_sizes; (void)n_in; (void)out_size;
}

// round 17
// speedup vs baseline: 1.0264x; 1.0193x over previous
#include <cuda_runtime.h>
#include <cuda_fp16.h>
#include <math.h>
#include <stdint.h>

#define B_   8
#define N1_  4096
#define N2_  256
#define D_   1024
#define INNER_ 1024
#define HEADS_ 16
#define DH_  64
#define L_   (N1_ + N2_)
#define EPS_ 1e-5f

__device__ __half g_kvin16[(size_t)B_ * L_ * D_];
__device__ __half g_latm16[(size_t)B_ * N2_ * D_];
__device__ __half g_wq16 [(size_t)INNER_ * D_];
__device__ __half g_wkv16[(size_t)2 * INNER_ * D_];
__device__ __half g_wo16 [(size_t)D_ * INNER_];
__device__ __half g_att16[(size_t)B_ * N2_ * INNER_];
__device__ __half g_q16[(size_t)B_ * N2_ * INNER_];
__device__ __half g_k16[(size_t)B_ * L_ * INNER_];
__device__ __half g_v16[(size_t)B_ * L_ * INNER_];

__device__ __forceinline__ uint32_t smem_u32(const void* p) {
    uint32_t a;
    asm("{ .reg .u64 t; cvta.to.shared.u64 t, %1; cvt.u32.u64 %0, t; }" : "=r"(a) : "l"(p));
    return a;
}
#define CP_ASYNC16(dst, src) \
    asm volatile("cp.async.cg.shared.global [%0], [%1], 16;" :: "r"(dst), "l"(src))
#define CP_COMMIT() asm volatile("cp.async.commit_group;" ::: "memory")
#define CP_WAIT(n)  asm volatile("cp.async.wait_group %0;" :: "n"(n) : "memory")
#define LDSM_X4(r, addr) \
    asm volatile("ldmatrix.sync.aligned.m8n8.x4.shared.b16 {%0,%1,%2,%3}, [%4];" \
                 : "=r"((r)[0]), "=r"((r)[1]), "=r"((r)[2]), "=r"((r)[3]) : "r"(addr))
#define LDSM_X4_T(r, addr) \
    asm volatile("ldmatrix.sync.aligned.m8n8.x4.trans.shared.b16 {%0,%1,%2,%3}, [%4];" \
                 : "=r"((r)[0]), "=r"((r)[1]), "=r"((r)[2]), "=r"((r)[3]) : "r"(addr))
#define MMAF16(acc, a, b0, b1) \
    asm volatile("mma.sync.aligned.m16n8k16.row.col.f32.f16.f16.f32 " \
        "{%0,%1,%2,%3}, {%4,%5,%6,%7}, {%8,%9}, {%0,%1,%2,%3};" \
        : "+f"((acc)[0]), "+f"((acc)[1]), "+f"((acc)[2]), "+f"((acc)[3]) \
        : "r"((a)[0]), "r"((a)[1]), "r"((a)[2]), "r"((a)[3]), "r"(b0), "r"(b1))

#define GS_ROWB  80
#define GSA      10240
#define GS_STAGE 30720

// =============== GEMM core 128x256: 256 thr, warp 64x64, frag-preload, 1 sync/iter ===============
struct GemmAcc { float a[4][8][4]; };

__device__ __forceinline__ void gemm_tile(
    const __half* __restrict__ A16, const __half* __restrict__ B16,
    int bm, int bn, uint32_t smbase, GemmAcc& G)
{
    const int tid = threadIdx.x, wid = tid >> 5, lane = tid & 31;
    const int wm = (wid & 1) * 64, wn = (wid >> 1) * 64;
    const int K = D_;

    auto load_stage = [&](int kt, int st) {
        const uint32_t sb = smbase + st * GS_STAGE;
        #pragma unroll
        for (int it = 0; it < 6; it++) {
            const int c = tid + it * 256;
            const bool isA = c < 512;
            const int cc = isA ? c : c - 512;
            const int row = cc >> 2, col = cc & 3;
            const char* src = (isA
                ? (const char*)A16 + ((size_t)(bm + row) * K + kt * 32) * 2
                : (const char*)B16 + ((size_t)(bn + row) * K + kt * 32) * 2) + col * 16;
            CP_ASYNC16(sb + (isA ? 0u : (uint32_t)GSA) + row * GS_ROWB + col * 16, src);
        }
        CP_COMMIT();
    };

    #pragma unroll
    for (int i = 0; i < 4; i++)
        #pragma unroll
        for (int t = 0; t < 8; t++)
            #pragma unroll
            for (int c = 0; c < 4; c++) G.a[i][t][c] = 0.f;

    const int niter = K / 32;
    load_stage(0, 0);
    load_stage(1, 1);

    for (int kt = 0; kt < niter; kt++) {
        CP_WAIT(1);
        __syncthreads();                      // single sync per iter (orders stage reuse)
        if (kt + 2 < niter) load_stage(kt + 2, (kt + 2) % 3);

        const uint32_t base = smbase + (kt % 3) * GS_STAGE;
        uint32_t af[2][4][4], bf[2][4][4];
        // preload ALL fragments for this iter (32 LDSM), then dense MMA block
        #pragma unroll
        for (int kk = 0; kk < 2; kk++) {
            #pragma unroll
            for (int i = 0; i < 4; i++) {
                const uint32_t ra = base + (uint32_t)((wm + i * 16 + (lane & 15)) * GS_ROWB
                                    + ((lane >> 4) << 4) + kk * 32);
                LDSM_X4(af[kk][i], ra);
            }
            #pragma unroll
            for (int g = 0; g < 4; g++) {
                const uint32_t rb = base + GSA
                    + (uint32_t)((wn + g * 16 + ((lane >> 4) << 3) + (lane & 7)) * GS_ROWB
                                 + (((lane >> 3) & 1) << 4) + kk * 32);
                LDSM_X4(bf[kk][g], rb);
            }
        }
        #pragma unroll
        for (int kk = 0; kk < 2; kk++)
            #pragma unroll
            for (int i = 0; i < 4; i++)
                #pragma unroll
                for (int g = 0; g < 4; g++) {
                    MMAF16(G.a[i][2*g],   af[kk][i], bf[kk][g][0], bf[kk][g][1]);
                    MMAF16(G.a[i][2*g+1], af[kk][i], bf[kk][g][2], bf[kk][g][3]);
                }
    }
    __syncthreads();
}

// =============== fused projection kernel: q (64 CTAs) + kv (2176 CTAs) ===============
__global__ __launch_bounds__(256, 1)
void proj_kernel(const __half* __restrict__ kvin16, const __half* __restrict__ latm16,
                 const __half* __restrict__ wkv16, const __half* __restrict__ wq16,
                 __half* __restrict__ k16, __half* __restrict__ v16,
                 __half* __restrict__ q16)
{
    extern __shared__ char smraw[];
    const uint32_t smbase = smem_u32(smraw);
    const int tid = threadIdx.x, wid = tid >> 5, lane = tid & 31;
    const int wm = (wid & 1) * 64, wn = (wid >> 1) * 64;

    const bool is_q = blockIdx.x < 64;
    int bm, bn;
    const __half *A, *Bw;
    if (is_q) {
        bm = (blockIdx.x >> 2) * 128; bn = (blockIdx.x & 3) * 256;
        A = latm16; Bw = wq16;
    } else {
        const int j = blockIdx.x - 64;
        bm = (j >> 3) * 128; bn = (j & 7) * 256;
        A = kvin16; Bw = wkv16;
    }

    GemmAcc G;
    gemm_tile(A, Bw, bm, bn, smbase, G);

    #pragma unroll
    for (int i = 0; i < 4; i++)
        #pragma unroll
        for (int t = 0; t < 8; t++) {
            const int r0 = bm + wm + i * 16 + (lane >> 2);
            const int c  = bn + wn + t * 8 + (lane & 3) * 2;
            const float v0 = G.a[i][t][0], v1 = G.a[i][t][1];
            const float v2 = G.a[i][t][2], v3 = G.a[i][t][3];
            if (is_q) {
                *reinterpret_cast<__half2*>(&q16[(size_t)r0*INNER_ + c]) = __floats2half2_rn(v0, v1);
                *reinterpret_cast<__half2*>(&q16[(size_t)(r0+8)*INNER_ + c]) = __floats2half2_rn(v2, v3);
            } else {
                __half* dst = (c < INNER_) ? k16 : v16;
                const int cc = (c < INNER_) ? c : c - INNER_;
                *reinterpret_cast<__half2*>(&dst[(size_t)r0*INNER_ + cc]) = __floats2half2_rn(v0, v1);
                *reinterpret_cast<__half2*>(&dst[(size_t)(r0+8)*INNER_ + cc]) = __floats2half2_rn(v2, v3);
            }
        }
}

// =============== o-projection kernel: CTA 128x128, warp 32x64 (4x2), 128 CTAs ===============
#define OG_STAGE 20480

__global__ __launch_bounds__(256, 1)
void ogemm_kernel(const __half* __restrict__ att16, const __half* __restrict__ wo16,
                  float* __restrict__ out)
{
    extern __shared__ char smraw[];
    const uint32_t smbase = smem_u32(smraw);
    const int tid = threadIdx.x, wid = tid >> 5, lane = tid & 31;
    const int bm = blockIdx.y * 128, bn = blockIdx.x * 128;
    const int wm = (wid & 3) * 32, wn = (wid >> 2) * 64;
    const int K = INNER_;

    auto load_stage = [&](int kt, int st) {
        const uint32_t sb = smbase + st * OG_STAGE;
        #pragma unroll
        for (int it = 0; it < 4; it++) {
            const int c = tid + it * 256;
            const bool isA = c < 512;
            const int cc = isA ? c : c - 512;
            const int row = cc >> 2, col = cc & 3;
            const char* src = (isA
                ? (const char*)att16 + ((size_t)(bm + row) * K + kt * 32) * 2
                : (const char*)wo16  + ((size_t)(bn + row) * K + kt * 32) * 2) + col * 16;
            CP_ASYNC16(sb + (isA ? 0u : (uint32_t)GSA) + row * GS_ROWB + col * 16, src);
        }
        CP_COMMIT();
    };

    float acc[2][8][4];
    #pragma unroll
    for (int i = 0; i < 2; i++)
        #pragma unroll
        for (int t = 0; t < 8; t++)
            #pragma unroll
            for (int c = 0; c < 4; c++) acc[i][t][c] = 0.f;

    const int niter = K / 32;
    load_stage(0, 0);
    load_stage(1, 1);

    for (int kt = 0; kt < niter; kt++) {
        CP_WAIT(1);
        __syncthreads();
        if (kt + 2 < niter) load_stage(kt + 2, (kt + 2) % 3);

        const uint32_t base = smbase + (kt % 3) * OG_STAGE;
        uint32_t af[2][2][4], bf[2][4][4];
        #pragma unroll
        for (int kk = 0; kk < 2; kk++) {
            #pragma unroll
            for (int i = 0; i < 2; i++) {
                const uint32_t ra = base + (uint32_t)((wm + i * 16 + (lane & 15)) * GS_ROWB
                                    + ((lane >> 4) << 4) + kk * 32);
                LDSM_X4(af[kk][i], ra);
            }
            #pragma unroll
            for (int g = 0; g < 4; g++) {
                const uint32_t rb = base + GSA
                    + (uint32_t)((wn + g * 16 + ((lane >> 4) << 3) + (lane & 7)) * GS_ROWB
                                 + (((lane >> 3) & 1) << 4) + kk * 32);
                LDSM_X4(bf[kk][g], rb);
            }
        }
        #pragma unroll
        for (int kk = 0; kk < 2; kk++)
            #pragma unroll
            for (int i = 0; i < 2; i++)
                #pragma unroll
                for (int g = 0; g < 4; g++) {
                    MMAF16(acc[i][2*g],   af[kk][i], bf[kk][g][0], bf[kk][g][1]);
                    MMAF16(acc[i][2*g+1], af[kk][i], bf[kk][g][2], bf[kk][g][3]);
                }
    }

    #pragma unroll
    for (int i = 0; i < 2; i++)
        #pragma unroll
        for (int t = 0; t < 8; t++) {
            const int r0 = bm + wm + i * 16 + (lane >> 2);
            const int c  = bn + wn + t * 8 + (lane & 3) * 2;
            *reinterpret_cast<float2*>(&out[(size_t)r0 * D_ + c]) =
                make_float2(acc[i][t][0], acc[i][t][1]);
            *reinterpret_cast<float2*>(&out[(size_t)(r0 + 8) * D_ + c]) =
                make_float2(acc[i][t][2], acc[i][t][3]);
        }
}

// =============== fused prep: LayerNorm(+mod) blocks + weight-conv blocks ===============
__global__ __launch_bounds__(256)
void prep_kernel(const float* __restrict__ x, const float* __restrict__ latents,
                 const float* __restrict__ shift, const float* __restrict__ scale,
                 const float* __restrict__ ln1w, const float* __restrict__ ln1b,
                 const float* __restrict__ ln2w, const float* __restrict__ ln2b,
                 const float* __restrict__ Wq, const float* __restrict__ Wkv,
                 const float* __restrict__ Wo, float qsc)
{
    const int t = threadIdx.x;
    if (blockIdx.x >= (unsigned)(B_ * L_)) {
        const int cb = blockIdx.x - B_ * L_;
        const float* s; __half* d; float sc; int i;
        if (cb < 1024)      { s = Wq;  d = g_wq16;  sc = qsc; i = cb * 256 + t; }
        else if (cb < 3072) { s = Wkv; d = g_wkv16; sc = 1.f; i = (cb - 1024) * 256 + t; }
        else                { s = Wo;  d = g_wo16;  sc = 1.f; i = (cb - 3072) * 256 + t; }
        float4 v = reinterpret_cast<const float4*>(s)[i];
        reinterpret_cast<__half2*>(d)[i*2]   = __floats2half2_rn(v.x * sc, v.y * sc);
        reinterpret_cast<__half2*>(d)[i*2+1] = __floats2half2_rn(v.z * sc, v.w * sc);
        return;
    }

    const int row = blockIdx.x, batch = row / L_, local = row % L_;
    const bool is_lat = (local >= N1_);
    const float* src = is_lat
        ? latents + ((size_t)batch * N2_ + (local - N1_)) * D_
        : x + ((size_t)batch * N1_ + local) * D_;

    float4 v = reinterpret_cast<const float4*>(src)[t];
    float s = v.x + v.y + v.z + v.w;
    float sq = v.x*v.x + v.y*v.y + v.z*v.z + v.w*v.w;

    __shared__ float red[16], red2[16];
    for (int o = 16; o > 0; o >>= 1) {
        s  += __shfl_down_sync(0xffffffff, s, o);
        sq += __shfl_down_sync(0xffffffff, sq, o);
    }
    int warp = t >> 5, lane = t & 31;
    if (lane == 0) { red[warp] = s; red2[warp] = sq; }
    __syncthreads();
    if (warp == 0) {
        s = (lane < 8) ? red[lane] : 0.f;
        sq = (lane < 8) ? red2[lane] : 0.f;
        for (int o = 4; o > 0; o >>= 1) {
            s  += __shfl_down_sync(0xffffffff, s, o);
            sq += __shfl_down_sync(0xffffffff, sq, o);
        }
        if (lane == 0) { red[0] = s; red2[0] = sq; }
    }
    __syncthreads();
    const float mu = red[0] * (1.0f / D_);
    const float var = red2[0] * (1.0f / D_) - mu * mu;
    const float rstd = rsqrtf(var + EPS_);

    float4 w4, b4, out;
    if (is_lat) {
        w4 = reinterpret_cast<const float4*>(ln2w)[t];
        b4 = reinterpret_cast<const float4*>(ln2b)[t];
    } else {
        w4 = reinterpret_cast<const float4*>(ln1w)[t];
        b4 = reinterpret_cast<const float4*>(ln1b)[t];
    }
    out.x = (v.x - mu) * rstd * w4.x + b4.x;
    out.y = (v.y - mu) * rstd * w4.y + b4.y;
    out.z = (v.z - mu) * rstd * w4.z + b4.z;
    out.w = (v.w - mu) * rstd * w4.w + b4.w;

    if (is_lat) {
        const float4 sc = reinterpret_cast<const float4*>(scale + (size_t)batch * D_)[t];
        const float4 sh = reinterpret_cast<const float4*>(shift + (size_t)batch * D_)[t];
        out.x = out.x * (1.0f + sc.x) + sh.x;
        out.y = out.y * (1.0f + sc.y) + sh.y;
        out.z = out.z * (1.0f + sc.z) + sh.z;
        out.w = out.w * (1.0f + sc.w) + sh.w;
    }

    __half2 hA = __floats2half2_rn(out.x, out.y);
    __half2 hB = __floats2half2_rn(out.z, out.w);
    {
        __half2* hp = reinterpret_cast<__half2*>(g_kvin16 + (size_t)row * D_);
        hp[t*2] = hA; hp[t*2+1] = hB;
    }
    if (is_lat) {
        const size_t lr = (size_t)batch * N2_ + (local - N1_);
        __half2* hp = reinterpret_cast<__half2*>(g_latm16 + lr * D_);
        hp[t*2] = hA; hp[t*2+1] = hB;
    }
}

// ============================ mma.sync flash attention (R14 version) ============================
#define AT_ROWB 144
#define AK_BASE 18432
#define AK_STAGE 18432
#define AV 9216
#define A_SMEM (18432 + 3 * 18432)

__global__ __launch_bounds__(256, 1)
void attn_mma(const __half* __restrict__ q16, const __half* __restrict__ k16,
              const __half* __restrict__ v16, __half* __restrict__ att)
{
    extern __shared__ char sm[];
    const uint32_t smb = smem_u32(sm);
    const int tid = threadIdx.x, wid = tid >> 5, lane = tid & 31;
    const int batch = blockIdx.x >> 4, head = blockIdx.x & 15;
    const int q0 = batch * N2_ + blockIdx.y * 128;
    const size_t kv0 = (size_t)batch * L_;

    for (int i = tid; i < 1024; i += 256) {
        const int row = i >> 3, ch = (i & 7) * 16;
        const size_t g = ((size_t)(q0 + row) * INNER_ + head * DH_) * 2;
        CP_ASYNC16(smb + row * AT_ROWB + ch, (const char*)q16 + g + ch);
    }
    CP_COMMIT();

    auto load_kv = [&](int t, int st) {
        const uint32_t sb = smb + AK_BASE + st * AK_STAGE;
        for (int i = tid; i < 512; i += 256) {
            const int row = i >> 3, ch = (i & 7) * 16;
            const size_t gr = kv0 + t * 64 + row;
            const size_t gk = (gr * INNER_ + head * DH_) * 2;
            CP_ASYNC16(sb + row * AT_ROWB + ch, (const char*)k16 + gk + ch);
            CP_ASYNC16(sb + AV + row * AT_ROWB + ch, (const char*)v16 + gk + ch);
        }
        CP_COMMIT();
    };

    const int NT = L_ / 64;
    load_kv(0, 0);
    load_kv(1, 1);
    CP_WAIT(1);
    __syncthreads();

    uint32_t qf[4][4];
    #pragma unroll
    for (int kk = 0; kk < 4; kk++) {
        const uint32_t ra = smb + (wid * 16 + (lane & 15)) * AT_ROWB + ((lane >> 4) << 4) + kk * 32;
        LDSM_X4(qf[kk], ra);
    }

    float accO[8][4];
    #pragma unroll
    for (int nt = 0; nt < 8; nt++)
        #pragma unroll
        for (int c = 0; c < 4; c++) accO[nt][c] = 0.f;
    float m0 = -1e30f, m1 = -1e30f, l0 = 0.f, l1 = 0.f;

    for (int t = 0; t < NT; t++) {
        if (t > 0) { CP_WAIT(1); __syncthreads(); }
        if (t + 2 < NT) load_kv(t + 2, (t + 2) % 3);
        const uint32_t sb = smb + AK_BASE + (t % 3) * AK_STAGE;

        float sacc[8][4];
        #pragma unroll
        for (int nt = 0; nt < 8; nt++)
            #pragma unroll
            for (int c = 0; c < 4; c++) sacc[nt][c] = 0.f;

        #pragma unroll
        for (int kk = 0; kk < 4; kk++) {
            uint32_t kb[4][4];
            #pragma unroll
            for (int g = 0; g < 4; g++) {
                const uint32_t rb = sb + (g * 16 + ((lane >> 4) << 3) + (lane & 7)) * AT_ROWB
                                    + (((lane >> 3) & 1) << 4) + kk * 32;
                LDSM_X4(kb[g], rb);
            }
            #pragma unroll
            for (int g = 0; g < 4; g++) {
                MMAF16(sacc[2*g],   qf[kk], kb[g][0], kb[g][1]);
                MMAF16(sacc[2*g+1], qf[kk], kb[g][2], kb[g][3]);
            }
        }

        float tm0 = sacc[0][0], tm1 = sacc[0][2];
        #pragma unroll
        for (int nt = 0; nt < 8; nt++) {
            tm0 = fmaxf(tm0, fmaxf(sacc[nt][0], sacc[nt][1]));
            tm1 = fmaxf(tm1, fmaxf(sacc[nt][2], sacc[nt][3]));
        }
        tm0 = fmaxf(tm0, __shfl_xor_sync(0xffffffff, tm0, 1));
        tm0 = fmaxf(tm0, __shfl_xor_sync(0xffffffff, tm0, 2));
        tm1 = fmaxf(tm1, __shfl_xor_sync(0xffffffff, tm1, 1));
        tm1 = fmaxf(tm1, __shfl_xor_sync(0xffffffff, tm1, 2));

        const float mn0 = fmaxf(m0, tm0), mn1 = fmaxf(m1, tm1);
        const float c0 = exp2f(m0 - mn0), c1 = exp2f(m1 - mn1);
        m0 = mn0; m1 = mn1;

        float ls0 = 0.f, ls1 = 0.f;
        uint32_t pa[4][4];
        #pragma unroll
        for (int nt = 0; nt < 8; nt++) {
            const float p0 = exp2f(sacc[nt][0] - mn0);
            const float p1 = exp2f(sacc[nt][1] - mn0);
            const float p2 = exp2f(sacc[nt][2] - mn1);
            const float p3 = exp2f(sacc[nt][3] - mn1);
            ls0 += p0 + p1; ls1 += p2 + p3;
            __half2 ha = __floats2half2_rn(p0, p1);
            __half2 hb = __floats2half2_rn(p2, p3);
            pa[nt >> 1][(nt & 1) * 2 + 0] = *reinterpret_cast<uint32_t*>(&ha);
            pa[nt >> 1][(nt & 1) * 2 + 1] = *reinterpret_cast<uint32_t*>(&hb);
        }
        l0 = l0 * c0 + ls0;
        l1 = l1 * c1 + ls1;
        #pragma unroll
        for (int nt = 0; nt < 8; nt++) {
            accO[nt][0] *= c0; accO[nt][1] *= c0;
            accO[nt][2] *= c1; accO[nt][3] *= c1;
        }

        #pragma unroll
        for (int kt = 0; kt < 4; kt++) {
            uint32_t vb[4][4];
            #pragma unroll
            for (int g = 0; g < 4; g++) {
                const uint32_t rv = sb + AV + (kt * 16 + (lane & 15)) * AT_ROWB
                                    + g * 32 + ((lane >> 4) << 4);
                LDSM_X4_T(vb[g], rv);
            }
            #pragma unroll
            for (int g = 0; g < 4; g++) {
                MMAF16(accO[2*g],   pa[kt], vb[g][0], vb[g][1]);
                MMAF16(accO[2*g+1], pa[kt], vb[g][2], vb[g][3]);
            }
        }
    }

    l0 += __shfl_xor_sync(0xffffffff, l0, 1);
    l0 += __shfl_xor_sync(0xffffffff, l0, 2);
    l1 += __shfl_xor_sync(0xffffffff, l1, 1);
    l1 += __shfl_xor_sync(0xffffffff, l1, 2);
    const float i0 = 1.0f / l0, i1 = 1.0f / l1;

    const int qrow = q0 + wid * 16 + (lane >> 2);
    #pragma unroll
    for (int nt = 0; nt < 8; nt++) {
        const int col = head * DH_ + nt * 8 + (lane & 3) * 2;
        *reinterpret_cast<__half2*>(att + (size_t)qrow*INNER_ + col) =
            __floats2half2_rn(accO[nt][0]*i0, accO[nt][1]*i0);
        *reinterpret_cast<__half2*>(att + (size_t)(qrow+8)*INNER_ + col) =
            __floats2half2_rn(accO[nt][2]*i1, accO[nt][3]*i1);
    }
}

// ---------------- launch ----------------
extern "C" void kernel_launch(void* const* d_in, const int* in_sizes, int n_in,
                              void* d_out, int out_size)
{
    const float* x       = (const float*)d_in[0];
    const float* latents = (const float*)d_in[1];
    const float* shift   = (const float*)d_in[2];
    const float* scale   = (const float*)d_in[3];
    const float* ln1w    = (const float*)d_in[4];
    const float* ln1b    = (const float*)d_in[5];
    const float* ln2w    = (const float*)d_in[6];
    const float* ln2b    = (const float*)d_in[7];
    const float* Wq      = (const float*)d_in[8];
    const float* Wkv     = (const float*)d_in[9];
    const float* Wo      = (const float*)d_in[10];
    float* out = (float*)d_out;

    __half *kvin16,*latm16,*wq16,*wkv16,*wo16,*att16,*q16,*k16,*v16;
    cudaGetSymbolAddress((void**)&kvin16, g_kvin16);
    cudaGetSymbolAddress((void**)&latm16, g_latm16);
    cudaGetSymbolAddress((void**)&wq16, g_wq16);
    cudaGetSymbolAddress((void**)&wkv16, g_wkv16);
    cudaGetSymbolAddress((void**)&wo16, g_wo16);
    cudaGetSymbolAddress((void**)&att16, g_att16);
    cudaGetSymbolAddress((void**)&q16, g_q16);
    cudaGetSymbolAddress((void**)&k16, g_k16);
    cudaGetSymbolAddress((void**)&v16, g_v16);

    cudaFuncSetAttribute(proj_kernel, cudaFuncAttributeMaxDynamicSharedMemorySize, 3 * GS_STAGE);
    cudaFuncSetAttribute(ogemm_kernel, cudaFuncAttributeMaxDynamicSharedMemorySize, 3 * OG_STAGE);
    cudaFuncSetAttribute(attn_mma, cudaFuncAttributeMaxDynamicSharedMemorySize, A_SMEM);

    const float qsc = 0.125f * 1.44269504088896340736f;  // attn_scale^2 * log2(e)

    prep_kernel<<<B_ * L_ + 4096, 256>>>(x, latents, shift, scale,
                                         ln1w, ln1b, ln2w, ln2b, Wq, Wkv, Wo, qsc);

    proj_kernel<<<64 + 2176, 256, 3 * GS_STAGE>>>(kvin16, latm16, wkv16, wq16,
                                                  k16, v16, q16);

    {
        dim3 grid(B_ * HEADS_, N2_ / 128);
        attn_mma<<<grid, 256, A_SMEM>>>(q16, k16, v16, att16);
    }

    {
        dim3 grid(D_ / 128, (B_ * N2_) / 128);
        ogemm_kernel<<<grid, 256, 3 * OG_STAGE>>>(att16, wo16, out);
    }
    (void)in_sizes; (void)n_in; (void)out_size;
}